// round 11
// baseline (speedup 1.0000x reference)
#include <cuda_runtime.h>

// Problem constants
#define Bb 2
#define Hh 16
#define Tt 2048
#define Dd 64
#define Rr 32
#define BHn (Bb*Hh)

#define BM 128
#define BN 64
#define NTHREADS 128
#define PS_STRIDE 132

#define SEG_TILES 8                    // 8 key-tiles (512 keys) per work segment
#define NSEG(m)   ((2*(m)+9)>>3)       // segments for item with mt=m (tiles=2m+2)
#define TOTSEG    1280                 // 32 bh * sum_mt NSEG(mt)
#define NBLK      444                  // 148 SMs * 3 blocks

// smem layout (floats)
#define QS_OFF 0                              // Qs[Rr][2*BM]  duplicated  8192
#define KS_OFF 8192                           // Ks[2][Rr][BN]             2x2048
#define VS_OFF (8192+4096)                    // Vs[BN][Dd] single, permuted 4096
#define PS_OFF (8192+4096+4096)               // Ps[16][132]               2112
#define KS_BUF 2048
#define SMEM_FLOATS (8192+4096+4096+16*PS_STRIDE)
#define SMEM_BYTES  (SMEM_FLOATS*4)           // 73984 B -> 3 blocks/SM

typedef unsigned long long u64;

// Low-rank projections: q duplicated [bh][r][2t], k normal [bh][r][t]
__device__ float g_qlr[(size_t)BHn * Rr * 2 * Tt];
__device__ float g_klr[(size_t)BHn * Rr * Tt];
// Split-K partial buffers
__device__ float g_pO[(size_t)TOTSEG * BM * Dd];
__device__ float g_pl[(size_t)TOTSEG * BM];
__device__ int   g_ctr;

// ---------- packed f32x2 helpers ----------
__device__ __forceinline__ u64 ffma2(u64 a, u64 b, u64 c) {
    u64 d;
    asm("fma.rn.f32x2 %0, %1, %2, %3;" : "=l"(d) : "l"(a), "l"(b), "l"(c));
    return d;
}
__device__ __forceinline__ u64 pack2(float x, float y) {
    u64 r;
    asm("mov.b64 %0, {%1, %2};" : "=l"(r) : "f"(x), "f"(y));
    return r;
}
__device__ __forceinline__ float2 unpack2(u64 a) {
    float2 f;
    asm("mov.b64 {%0, %1}, %2;" : "=f"(f.x), "=f"(f.y) : "l"(a));
    return f;
}
__device__ __forceinline__ float ex2(float x) {
    float r;
    asm("ex2.approx.ftz.f32 %0, %1;" : "=f"(r) : "f"(x));
    return r;
}
__device__ __forceinline__ unsigned smem_u32(const void* p) {
    unsigned a;
    asm("{ .reg .u64 t; cvta.to.shared.u64 t, %1; cvt.u32.u64 %0, t; }"
        : "=r"(a) : "l"(p));
    return a;
}
__device__ __forceinline__ void cp16(unsigned dst, const void* src) {
    asm volatile("cp.async.cg.shared.global [%0], [%1], 16;"
                 :: "r"(dst), "l"(src));
}

// ---------- Stage 1: fused q/k projection; q written DUPLICATED ----------
__global__ __launch_bounds__(256) void proj_kernel(
    const float* __restrict__ q, const float* __restrict__ k,
    const float* __restrict__ Wq, const float* __restrict__ Wk,
    const float* __restrict__ c1, const float* __restrict__ c2)
{
    __shared__ float xs[64 * 64];
    __shared__ float tsm[32][65];

    if (blockIdx.x == 0 && blockIdx.y == 0 && blockIdx.z == 0 && threadIdx.x == 0)
        g_ctr = NBLK;

    const int  is_q = (blockIdx.z == 0);
    const float* x  = is_q ? q  : k;
    const float* W  = is_q ? Wq : Wk;
    const int bh  = blockIdx.x;
    const int h   = bh & (Hh - 1);
    const int t0  = blockIdx.y * 64;
    const int tid = threadIdx.x;
    const int r   = tid & 31;
    const int wp  = tid >> 5;

    float wreg[64];
    const float* Wp = W + (size_t)h * Dd * Rr + r;
#pragma unroll
    for (int d = 0; d < 64; d++) wreg[d] = Wp[d * Rr];

    {
        const float4* xg = (const float4*)(x + ((size_t)bh * Tt + t0) * Dd);
        float4* xs4 = (float4*)xs;
#pragma unroll
        for (int i = 0; i < 4; i++) xs4[tid + 256 * i] = xg[tid + 256 * i];
    }
    __syncthreads();

    float mult = 1.0f;
    if (is_q) {
        mult = c1[h * 4 + (r >> 3)] * c2[h * 8 + (r & 7)]
             * (0.17677669529663687f * 1.4426950408889634f);   // scale * log2(e)
    }

    for (int tt = wp; tt < 64; tt += 8) {
        const float4* xr = (const float4*)(xs + tt * 64);
        float acc = 0.0f;
#pragma unroll
        for (int d4 = 0; d4 < 16; d4++) {
            float4 xv = xr[d4];
            acc = fmaf(xv.x, wreg[4 * d4 + 0], acc);
            acc = fmaf(xv.y, wreg[4 * d4 + 1], acc);
            acc = fmaf(xv.z, wreg[4 * d4 + 2], acc);
            acc = fmaf(xv.w, wreg[4 * d4 + 3], acc);
        }
        tsm[r][tt] = acc * mult;
    }
    __syncthreads();

    const int rr = tid >> 3;
    const int c0 = (tid & 7) * 8;
    if (is_q) {
        // duplicated pairs {v,v}: row length 2*Tt
        float* outp = g_qlr + (size_t)bh * Rr * 2 * Tt + (size_t)rr * 2 * Tt
                    + 2 * (t0 + c0);
#pragma unroll
        for (int i = 0; i < 4; i++) {
            float v0 = tsm[rr][c0 + 2 * i];
            float v1 = tsm[rr][c0 + 2 * i + 1];
            *(float4*)(outp + 4 * i) = make_float4(v0, v0, v1, v1);
        }
    } else {
        float* outp = g_klr + (size_t)bh * Rr * Tt;
#pragma unroll
        for (int i = 0; i < 2; i++) {
            float4 vv = make_float4(tsm[rr][c0 + 4 * i + 0], tsm[rr][c0 + 4 * i + 1],
                                    tsm[rr][c0 + 4 * i + 2], tsm[rr][c0 + 4 * i + 3]);
            *(float4*)(outp + (size_t)rr * Tt + t0 + c0 + 4 * i) = vv;
        }
    }
}

// decode segment slot id -> (mt, bh, tile range). Heavy mt first.
__device__ __forceinline__ void decode_seg(int id, int& mt, int& bh,
                                           int& tbeg, int& tend)
{
    int rem = id, m = 15;
    while (true) {
        int ns  = NSEG(m);
        int cnt = ns << 5;
        if (rem < cnt) { mt = m; bh = rem / ns; int seg = rem % ns;
                         tbeg = seg * SEG_TILES;
                         tend = min(tbeg + SEG_TILES, 2 * m + 2);
                         return; }
        rem -= cnt; m--;
    }
}

// ---------- Stage 2: persistent split-K flash; duplicated-Q score GEMM ----------
__global__ __launch_bounds__(NTHREADS, 3) void flash_kernel(
    const float* __restrict__ v)
{
    extern __shared__ float sm[];
    float* Qs = sm + QS_OFF;   // [Rr][256] duplicated
    float* Vs = sm + VS_OFF;   // single buffer, permuted rows
    float* Ps = sm + PS_OFF;
    __shared__ int s_slot;

    const int tid = threadIdx.x;
    const int tn  = tid & 7;
    const int tm  = tid >> 3;
    const int wid = tid >> 5;

    const unsigned qs_u32 = smem_u32(sm + QS_OFF);
    const unsigned ks_u32 = smem_u32(sm + KS_OFF);
    const unsigned vs_u32 = smem_u32(sm + VS_OFF);
    const float NEG_INF = __int_as_float(0xff800000);

    int slot = blockIdx.x;
    while (slot < TOTSEG) {
        int mt, bh, tbeg, tend;
        decode_seg(slot, mt, bh, tbeg, tend);
        const int m0 = mt * BM;

        const float* kg_base = g_klr + (size_t)bh * Rr * Tt;
        const float* vg_base = v + (size_t)bh * Tt * Dd;

        auto issue_K = [&](int nt) {    // K tile -> buffer nt&1 (no commit)
            const float* kg = kg_base + nt * BN;
            const unsigned kb = ks_u32 + (unsigned)((nt & 1) * KS_BUF * 4);
#pragma unroll
            for (int it = 0; it < 4; it++) {
                int idx = tid + 128 * it;
                int rr  = idx >> 4;
                int cc  = (idx & 15) * 4;
                cp16(kb + (unsigned)((rr * BN + cc) * 4), kg + (size_t)rr * Tt + cc);
            }
        };
        auto issue_V = [&](int nt) {    // V tile -> single buffer (no commit)
            const float* vg = vg_base + (size_t)(nt * BN) * Dd;
#pragma unroll
            for (int it = 0; it < 8; it++) {
                int idx = tid + 128 * it;
                int row = idx >> 4;
                int cc  = (idx & 15) * 4;
                int pr  = (((row & 3) + ((row >> 5) << 2)) << 3) + ((row >> 2) & 7);
                cp16(vs_u32 + (unsigned)((pr * Dd + cc) * 4), vg + row * Dd + cc);
            }
        };

        __syncthreads();   // prior segment's smem reads complete

        // group 1: Q (duplicated rows) + K(tbeg);  group 2: V(tbeg)
        {
            const float* qgd = g_qlr + (size_t)bh * Rr * 2 * Tt + 2 * m0;
#pragma unroll
            for (int it = 0; it < 16; it++) {
                int idx = tid + 128 * it;          // 2048 16B chunks
                int rr  = idx >> 6;
                int cc  = (idx & 63) * 4;
                cp16(qs_u32 + (unsigned)(idx * 16), qgd + (size_t)rr * 2 * Tt + cc);
            }
            issue_K(tbeg);
            asm volatile("cp.async.commit_group;");
            issue_V(tbeg);
            asm volatile("cp.async.commit_group;");
        }

        u64 o2[8][4];
#pragma unroll
        for (int i = 0; i < 8; i++)
#pragma unroll
            for (int p = 0; p < 4; p++) o2[i][p] = 0ull;
        float l[8];
#pragma unroll
        for (int i = 0; i < 8; i++) l[i] = 0.0f;

        for (int nt = tbeg; nt < tend; nt++) {
            const int n0 = nt * BN;
            float* Ks = sm + KS_OFF + (nt & 1) * KS_BUF;
            const bool more = (nt + 1 < tend);
            const bool skip = (m0 + 32 * wid + 31 < n0);   // fully-masked warp
            const bool diag = (nt >= 2 * mt);

            // ---- wait K(nt) (+Q on first tile); V may still be in flight ----
            asm volatile("cp.async.wait_group 1;");
            __syncthreads();
            if (more) { issue_K(nt + 1); asm volatile("cp.async.commit_group;"); }

            // score chunk: 5 LDS.128 + 16 FFMA2 per r, zero packs
            auto score_chunk = [&](int cbase, float s[8][4]) {
                u64 acc[8][2];
#pragma unroll
                for (int i = 0; i < 8; i++) { acc[i][0] = 0ull; acc[i][1] = 0ull; }
#pragma unroll 8
                for (int r = 0; r < Rr; r++) {
                    const ulonglong2* qrow =
                        (const ulonglong2*)(Qs + r * 256 + tm * 16);
                    ulonglong2 A0 = qrow[0];
                    ulonglong2 A1 = qrow[1];
                    ulonglong2 A2 = qrow[2];
                    ulonglong2 A3 = qrow[3];
                    ulonglong2 K0 = *(const ulonglong2*)(Ks + r * BN + cbase + tn * 4);
                    acc[0][0] = ffma2(A0.x, K0.x, acc[0][0]);
                    acc[0][1] = ffma2(A0.x, K0.y, acc[0][1]);
                    acc[1][0] = ffma2(A0.y, K0.x, acc[1][0]);
                    acc[1][1] = ffma2(A0.y, K0.y, acc[1][1]);
                    acc[2][0] = ffma2(A1.x, K0.x, acc[2][0]);
                    acc[2][1] = ffma2(A1.x, K0.y, acc[2][1]);
                    acc[3][0] = ffma2(A1.y, K0.x, acc[3][0]);
                    acc[3][1] = ffma2(A1.y, K0.y, acc[3][1]);
                    acc[4][0] = ffma2(A2.x, K0.x, acc[4][0]);
                    acc[4][1] = ffma2(A2.x, K0.y, acc[4][1]);
                    acc[5][0] = ffma2(A2.y, K0.x, acc[5][0]);
                    acc[5][1] = ffma2(A2.y, K0.y, acc[5][1]);
                    acc[6][0] = ffma2(A3.x, K0.x, acc[6][0]);
                    acc[6][1] = ffma2(A3.x, K0.y, acc[6][1]);
                    acc[7][0] = ffma2(A3.y, K0.x, acc[7][0]);
                    acc[7][1] = ffma2(A3.y, K0.y, acc[7][1]);
                }
#pragma unroll
                for (int i = 0; i < 8; i++) {
                    float2 u0 = unpack2(acc[i][0]);
                    float2 u1 = unpack2(acc[i][1]);
                    s[i][0] = u0.x; s[i][1] = u0.y; s[i][2] = u1.x; s[i][3] = u1.y;
                }
                if (diag) {
#pragma unroll
                    for (int i = 0; i < 8; i++) {
                        const int row = m0 + tm * 8 + i;
#pragma unroll
                        for (int j = 0; j < 4; j++)
                            if (n0 + cbase + tn * 4 + j > row) s[i][j] = NEG_INF;
                    }
                }
#pragma unroll
                for (int i = 0; i < 8; i++) {
#pragma unroll
                    for (int j = 0; j < 4; j++) s[i][j] = ex2(s[i][j]);
                    l[i] += (s[i][0] + s[i][1]) + (s[i][2] + s[i][3]);
                }
            };
            // PV quarters through the warp-private Ps buffer
            auto pv_chunk = [&](int ch, const float s[8][4]) {
#pragma unroll
                for (int half = 0; half < 2; half++) {
                    const int qq = ch * 2 + half;
#pragma unroll
                    for (int jq = 0; jq < 2; jq++) {
                        const int j = half * 2 + jq;
                        float* base = Ps + (jq * 8 + tn) * PS_STRIDE + tm * 8;
                        *(float4*)base       = make_float4(s[0][j], s[1][j], s[2][j], s[3][j]);
                        *(float4*)(base + 4) = make_float4(s[4][j], s[5][j], s[6][j], s[7][j]);
                    }
                    __syncwarp();
#pragma unroll 8
                    for (int prl = 0; prl < 16; prl++) {
                        const float* prow = Ps + prl * PS_STRIDE + tm * 8;
                        float4 P0 = *(const float4*)prow;
                        float4 P1 = *(const float4*)(prow + 4);
                        const float* vrow = Vs + (qq * 16 + prl) * Dd + tn * 4;
                        ulonglong2 V0 = *(const ulonglong2*)vrow;
                        ulonglong2 V1 = *(const ulonglong2*)(vrow + 32);
                        float pv[8] = {P0.x, P0.y, P0.z, P0.w, P1.x, P1.y, P1.z, P1.w};
#pragma unroll
                        for (int i = 0; i < 8; i++) {
                            u64 pp = pack2(pv[i], pv[i]);
                            o2[i][0] = ffma2(pp, V0.x, o2[i][0]);
                            o2[i][1] = ffma2(pp, V0.y, o2[i][1]);
                            o2[i][2] = ffma2(pp, V1.x, o2[i][2]);
                            o2[i][3] = ffma2(pp, V1.y, o2[i][3]);
                        }
                    }
                    __syncwarp();
                }
            };

            float s[8][4];
            if (!skip) score_chunk(0, s);     // chunk-0 score overlaps V in flight

            // ---- wait V(nt) ----
            if (more) asm volatile("cp.async.wait_group 1;");
            else      asm volatile("cp.async.wait_group 0;");
            __syncthreads();

            if (!skip) {
                pv_chunk(0, s);
                score_chunk(32, s);
                pv_chunk(1, s);
            }

            __syncthreads();                  // all PV reads of Vs complete
            if (more) { issue_V(nt + 1); asm volatile("cp.async.commit_group;"); }
        }

        // ---- store unnormalized partials for this segment slot ----
        {
            float* po = g_pO + (size_t)slot * BM * Dd;
#pragma unroll
            for (int i = 0; i < 8; i++) {
#pragma unroll
                for (int d = 1; d < 8; d <<= 1)
                    l[i] += __shfl_xor_sync(0xffffffffu, l[i], d);
                const int row = tm * 8 + i;
                float* og = po + row * Dd;
                float2 a = unpack2(o2[i][0]);
                float2 b = unpack2(o2[i][1]);
                float2 c = unpack2(o2[i][2]);
                float2 d2 = unpack2(o2[i][3]);
                *(float4*)(og + tn * 4)      = make_float4(a.x, a.y, b.x, b.y);
                *(float4*)(og + 32 + tn * 4) = make_float4(c.x, c.y, d2.x, d2.y);
            }
            if (tn == 0) {
                float* pl = g_pl + (size_t)slot * BM;
#pragma unroll
                for (int i = 0; i < 8; i++) pl[tm * 8 + i] = l[i];
            }
        }

        // block-uniform queue pop
        __syncthreads();
        if (tid == 0) s_slot = atomicAdd(&g_ctr, 1);
        __syncthreads();
        slot = s_slot;
    }
}

// ---------- Stage 3: combine split-K partials, normalize ----------
__global__ __launch_bounds__(256) void combine_kernel(float* __restrict__ out)
{
    const int item = blockIdx.x;
    const int mt = item & 15;
    const int bh = item >> 4;
    const int nseg = NSEG(mt);

    int base = 0;
    for (int m = 15; m > mt; m--) base += NSEG(m) << 5;
    base += bh * nseg;

    const int tid  = threadIdx.x;
    const int rowl = blockIdx.y * 32 + (tid >> 3);
    const int dcol = (tid & 7) * 8;

    float lsum = 0.0f;
    float4 s0 = make_float4(0.f, 0.f, 0.f, 0.f);
    float4 s1 = make_float4(0.f, 0.f, 0.f, 0.f);
    for (int sgi = 0; sgi < nseg; sgi++) {
        const int slot = base + sgi;
        lsum += g_pl[(size_t)slot * BM + rowl];
        const float* po = g_pO + (size_t)slot * BM * Dd + rowl * Dd + dcol;
        float4 a = *(const float4*)po;
        float4 b = *(const float4*)(po + 4);
        s0.x += a.x; s0.y += a.y; s0.z += a.z; s0.w += a.w;
        s1.x += b.x; s1.y += b.y; s1.z += b.z; s1.w += b.w;
    }
    const float inv = 1.0f / lsum;
    const int row_g = mt * BM + rowl;
    float* og = out + ((size_t)bh * Tt + row_g) * Dd + dcol;
    *(float4*)og       = make_float4(s0.x * inv, s0.y * inv, s0.z * inv, s0.w * inv);
    *(float4*)(og + 4) = make_float4(s1.x * inv, s1.y * inv, s1.z * inv, s1.w * inv);
}

// ---------- launch ----------
extern "C" void kernel_launch(void* const* d_in, const int* in_sizes, int n_in,
                              void* d_out, int out_size)
{
    const float* q  = (const float*)d_in[0];
    const float* k  = (const float*)d_in[1];
    const float* v  = (const float*)d_in[2];
    const float* Wq = (const float*)d_in[3];
    const float* Wk = (const float*)d_in[4];
    const float* c1 = (const float*)d_in[5];
    const float* c2 = (const float*)d_in[6];
    float* out = (float*)d_out;

    cudaFuncSetAttribute(flash_kernel,
                         cudaFuncAttributeMaxDynamicSharedMemorySize, SMEM_BYTES);

    dim3 pg(BHn, Tt / 64, 2);
    proj_kernel<<<pg, 256>>>(q, k, Wq, Wk, c1, c2);

    flash_kernel<<<NBLK, NTHREADS, SMEM_BYTES>>>(v);

    dim3 cg(BHn * 16, 4);
    combine_kernel<<<cg, 256>>>(out);
}

// round 12
// speedup vs baseline: 1.0189x; 1.0189x over previous
#include <cuda_runtime.h>

// Problem constants
#define Bb 2
#define Hh 16
#define Tt 2048
#define Dd 64
#define Rr 32
#define BHn (Bb*Hh)

#define BM 128
#define BN 64
#define NTHREADS 128
#define PS_STRIDE 132

#define SEG_TILES 8                    // 8 key-tiles (512 keys) per work segment
#define NSEG(m)   ((2*(m)+9)>>3)       // segments for item with mt=m (tiles=2m+2)
#define TOTSEG    1280                 // 32 bh * sum_mt NSEG(mt)
#define NBLK      444                  // 148 SMs * 3 blocks

// smem layout (floats) — identical to R10 (73984 B -> 3 blocks/SM)
#define QS_OFF 0                              // Qs[Rr][BM]      4096
#define KS_OFF 4096                           // Ks[2][Rr][BN]   2x2048
#define VS_OFF (4096+4096)                    // Vs[2][BN][Dd]   2x4096 (row-permuted)
#define PS_OFF (4096+4096+8192)               // Ps[16][132]     2112 (quarter buffer)
#define KS_BUF 2048
#define VS_BUF 4096
#define SMEM_FLOATS (4096+4096+8192+16*PS_STRIDE)
#define SMEM_BYTES  (SMEM_FLOATS*4)

typedef unsigned long long u64;

// Low-rank projections stored TRANSPOSED: [bh][r][t]
__device__ float g_qlr[(size_t)BHn * Rr * Tt];
__device__ float g_klr[(size_t)BHn * Rr * Tt];
// Split-K partial buffers
__device__ float g_pO[(size_t)TOTSEG * BM * Dd];
__device__ float g_pl[(size_t)TOTSEG * BM];
__device__ int   g_ctr;

// ---------- packed f32x2 helpers ----------
__device__ __forceinline__ u64 ffma2(u64 a, u64 b, u64 c) {
    u64 d;
    asm("fma.rn.f32x2 %0, %1, %2, %3;" : "=l"(d) : "l"(a), "l"(b), "l"(c));
    return d;
}
__device__ __forceinline__ u64 pack2(float x, float y) {
    u64 r;
    asm("mov.b64 %0, {%1, %2};" : "=l"(r) : "f"(x), "f"(y));
    return r;
}
__device__ __forceinline__ float2 unpack2(u64 a) {
    float2 f;
    asm("mov.b64 {%0, %1}, %2;" : "=f"(f.x), "=f"(f.y) : "l"(a));
    return f;
}
__device__ __forceinline__ float ex2(float x) {
    float r;
    asm("ex2.approx.ftz.f32 %0, %1;" : "=f"(r) : "f"(x));
    return r;
}
__device__ __forceinline__ unsigned smem_u32(const void* p) {
    unsigned a;
    asm("{ .reg .u64 t; cvta.to.shared.u64 t, %1; cvt.u32.u64 %0, t; }"
        : "=r"(a) : "l"(p));
    return a;
}
__device__ __forceinline__ void cp16(unsigned dst, const void* src) {
    asm volatile("cp.async.cg.shared.global [%0], [%1], 16;"
                 :: "r"(dst), "l"(src));
}

// ---------- Stage 1: fused q/k projection (W staged coalesced via smem) ----------
__global__ __launch_bounds__(256) void proj_kernel(
    const float* __restrict__ q, const float* __restrict__ k,
    const float* __restrict__ Wq, const float* __restrict__ Wk,
    const float* __restrict__ c1, const float* __restrict__ c2)
{
    __shared__ float xs[64 * 64];
    __shared__ float tsm[32][65];
    __shared__ float Wsm[Dd * Rr];    // 2048 floats

    if (blockIdx.x == 0 && blockIdx.y == 0 && blockIdx.z == 0 && threadIdx.x == 0)
        g_ctr = NBLK;

    const int  is_q = (blockIdx.z == 0);
    const float* x  = is_q ? q  : k;
    const float* W  = is_q ? Wq : Wk;
    const int bh  = blockIdx.x;
    const int h   = bh & (Hh - 1);
    const int t0  = blockIdx.y * 64;
    const int tid = threadIdx.x;
    const int r   = tid & 31;
    const int wp  = tid >> 5;

    // stage W coalesced (512 float4, 256 threads -> 2 each) + x rows
    {
        const float4* Wg = (const float4*)(W + (size_t)h * Dd * Rr);
        float4* Ws4 = (float4*)Wsm;
        Ws4[tid]       = Wg[tid];
        Ws4[tid + 256] = Wg[tid + 256];

        const float4* xg = (const float4*)(x + ((size_t)bh * Tt + t0) * Dd);
        float4* xs4 = (float4*)xs;
#pragma unroll
        for (int i = 0; i < 4; i++) xs4[tid + 256 * i] = xg[tid + 256 * i];
    }
    __syncthreads();

    // per-thread W column from smem (conflict-free: lane = r)
    float wreg[64];
#pragma unroll
    for (int d = 0; d < 64; d++) wreg[d] = Wsm[d * Rr + r];

    float mult = 1.0f;
    if (is_q) {
        mult = c1[h * 4 + (r >> 3)] * c2[h * 8 + (r & 7)]
             * (0.17677669529663687f * 1.4426950408889634f);   // scale * log2(e)
    }

    for (int tt = wp; tt < 64; tt += 8) {
        const float4* xr = (const float4*)(xs + tt * 64);
        float acc = 0.0f;
#pragma unroll
        for (int d4 = 0; d4 < 16; d4++) {
            float4 xv = xr[d4];
            acc = fmaf(xv.x, wreg[4 * d4 + 0], acc);
            acc = fmaf(xv.y, wreg[4 * d4 + 1], acc);
            acc = fmaf(xv.z, wreg[4 * d4 + 2], acc);
            acc = fmaf(xv.w, wreg[4 * d4 + 3], acc);
        }
        tsm[r][tt] = acc * mult;
    }
    __syncthreads();

    float* outp = (is_q ? g_qlr : g_klr) + (size_t)bh * Rr * Tt;
    const int rr = tid >> 3;
    const int c0 = (tid & 7) * 8;
#pragma unroll
    for (int i = 0; i < 2; i++) {
        float4 vv = make_float4(tsm[rr][c0 + 4 * i + 0], tsm[rr][c0 + 4 * i + 1],
                                tsm[rr][c0 + 4 * i + 2], tsm[rr][c0 + 4 * i + 3]);
        *(float4*)(outp + (size_t)rr * Tt + t0 + c0 + 4 * i) = vv;
    }
}

// decode segment slot id -> (mt, bh, tile range). Heavy mt first.
__device__ __forceinline__ void decode_seg(int id, int& mt, int& bh,
                                           int& tbeg, int& tend)
{
    int rem = id, m = 15;
    while (true) {
        int ns  = NSEG(m);
        int cnt = ns << 5;
        if (rem < cnt) { mt = m; bh = rem / ns; int seg = rem % ns;
                         tbeg = seg * SEG_TILES;
                         tend = min(tbeg + SEG_TILES, 2 * m + 2);
                         return; }
        rem -= cnt; m--;
    }
}

// ---------- Stage 2: persistent split-K flash; m-chunked score (half the packs) ----------
__global__ __launch_bounds__(NTHREADS, 3) void flash_kernel(
    const float* __restrict__ v)
{
    extern __shared__ float sm[];
    float* Qs = sm + QS_OFF;
    float* Ps = sm + PS_OFF;
    __shared__ int s_slot;

    const int tid = threadIdx.x;
    const int tn  = tid & 7;
    const int tm  = tid >> 3;
    const int wid = tid >> 5;

    const unsigned ks_u32 = smem_u32(sm + KS_OFF);
    const unsigned vs_u32 = smem_u32(sm + VS_OFF);
    const float NEG_INF = __int_as_float(0xff800000);

    int slot = blockIdx.x;
    while (slot < TOTSEG) {
        int mt, bh, tbeg, tend;
        decode_seg(slot, mt, bh, tbeg, tend);
        const int m0 = mt * BM;

        const float* kg_base = g_klr + (size_t)bh * Rr * Tt;
        const float* vg_base = v + (size_t)bh * Tt * Dd;

        // prefetch of K/V tile nt into buffer nt&1 (one commit group)
        auto issue_tile = [&](int nt) {
            const int n0 = nt * BN;
            const float* kg = kg_base + n0;
            const unsigned kb = ks_u32 + (unsigned)((nt & 1) * KS_BUF * 4);
#pragma unroll
            for (int it = 0; it < 4; it++) {
                int idx = tid + 128 * it;
                int rr  = idx >> 4;
                int cc  = (idx & 15) * 4;
                cp16(kb + (unsigned)((rr * BN + cc) * 4), kg + (size_t)rr * Tt + cc);
            }
            const float* vg = vg_base + (size_t)n0 * Dd;
            const unsigned vb = vs_u32 + (unsigned)((nt & 1) * VS_BUF * 4);
#pragma unroll
            for (int it = 0; it < 8; it++) {
                int idx = tid + 128 * it;
                int row = idx >> 4;
                int cc  = (idx & 15) * 4;
                int pr  = (((row & 3) + ((row >> 5) << 2)) << 3) + ((row >> 2) & 7);
                cp16(vb + (unsigned)((pr * Dd + cc) * 4), vg + row * Dd + cc);
            }
            asm volatile("cp.async.commit_group;");
        };

        __syncthreads();   // prior segment's smem reads complete

        // Q tile fill: Qs[r][m]
        {
            const float* qg = g_qlr + (size_t)bh * Rr * Tt + m0;
#pragma unroll
            for (int it = 0; it < 8; it++) {
                int idx = tid + 128 * it;
                int rr  = idx >> 5;
                int cc  = (idx & 31) * 4;
                *(float4*)(Qs + rr * BM + cc) = *(const float4*)(qg + (size_t)rr * Tt + cc);
            }
        }
        issue_tile(tbeg);

        u64 o2[8][4];
#pragma unroll
        for (int i = 0; i < 8; i++)
#pragma unroll
            for (int p = 0; p < 4; p++) o2[i][p] = 0ull;
        float l[8];
#pragma unroll
        for (int i = 0; i < 8; i++) l[i] = 0.0f;

        for (int nt = tbeg; nt < tend; nt++) {
            const int n0 = nt * BN;
            float* Ks = sm + KS_OFF + (nt & 1) * KS_BUF;
            float* Vs = sm + VS_OFF + (nt & 1) * VS_BUF;

            asm volatile("cp.async.wait_group 0;");
            __syncthreads();
            if (nt + 1 < tend) issue_tile(nt + 1);

            // warp-level causal skip (fully-masked warp on diagonal tiles)
            if (m0 + 32 * wid + 31 >= n0) {
                const bool diag = (nt >= 2 * mt);

                // ---- two m-chunks: 4 m-rows x 8 n-cols each ----
#pragma unroll
                for (int mc = 0; mc < 2; mc++) {
                    u64 acc[4][4];
#pragma unroll
                    for (int i = 0; i < 4; i++)
#pragma unroll
                        for (int p = 0; p < 4; p++) acc[i][p] = 0ull;

#pragma unroll 8
                    for (int r = 0; r < Rr; r++) {
                        float4 a = *(const float4*)(Qs + r * BM + tm * 8 + mc * 4);
                        const float* krow = Ks + r * BN + tn * 4;
                        ulonglong2 K0 = *(const ulonglong2*)krow;
                        ulonglong2 K1 = *(const ulonglong2*)(krow + 32);
                        float av[4] = {a.x, a.y, a.z, a.w};
#pragma unroll
                        for (int i = 0; i < 4; i++) {
                            u64 pa = pack2(av[i], av[i]);
                            acc[i][0] = ffma2(pa, K0.x, acc[i][0]);
                            acc[i][1] = ffma2(pa, K0.y, acc[i][1]);
                            acc[i][2] = ffma2(pa, K1.x, acc[i][2]);
                            acc[i][3] = ffma2(pa, K1.y, acc[i][3]);
                        }
                    }

                    // unpack: j 0..3 -> keys n0+tn*4+j, j 4..7 -> keys n0+32+tn*4+(j-4)
                    float s[4][8];
#pragma unroll
                    for (int i = 0; i < 4; i++) {
#pragma unroll
                        for (int p = 0; p < 4; p++) {
                            float2 u = unpack2(acc[i][p]);
                            s[i][2 * p]     = u.x;
                            s[i][2 * p + 1] = u.y;
                        }
                    }
                    if (diag) {
#pragma unroll
                        for (int i = 0; i < 4; i++) {
                            const int row = m0 + tm * 8 + mc * 4 + i;
#pragma unroll
                            for (int j = 0; j < 8; j++) {
                                int key = n0 + ((j < 4) ? (tn * 4 + j)
                                                        : (32 + tn * 4 + j - 4));
                                if (key > row) s[i][j] = NEG_INF;
                            }
                        }
                    }
#pragma unroll
                    for (int i = 0; i < 4; i++) {
#pragma unroll
                        for (int j = 0; j < 8; j++) s[i][j] = ex2(s[i][j]);
                        l[mc * 4 + i] += (s[i][0] + s[i][1]) + (s[i][2] + s[i][3])
                                       + (s[i][4] + s[i][5]) + (s[i][6] + s[i][7]);
                    }

                    // ---- P-store + PV per quarter (16 key rows), this m-chunk ----
#pragma unroll
                    for (int qq = 0; qq < 4; qq++) {
                        const int ch = qq >> 1, half = qq & 1;
#pragma unroll
                        for (int jq = 0; jq < 2; jq++) {
                            const int j = ch * 4 + half * 2 + jq;
                            *(float4*)(Ps + (jq * 8 + tn) * PS_STRIDE + tm * 8 + mc * 4) =
                                make_float4(s[0][j], s[1][j], s[2][j], s[3][j]);
                        }
                        __syncwarp();

#pragma unroll 8
                        for (int prl = 0; prl < 16; prl++) {
                            float4 P0 = *(const float4*)(Ps + prl * PS_STRIDE + tm * 8 + mc * 4);
                            const float* vrow = Vs + (qq * 16 + prl) * Dd + tn * 4;
                            ulonglong2 V0 = *(const ulonglong2*)vrow;
                            ulonglong2 V1 = *(const ulonglong2*)(vrow + 32);
                            float pv[4] = {P0.x, P0.y, P0.z, P0.w};
#pragma unroll
                            for (int i = 0; i < 4; i++) {
                                u64 pp = pack2(pv[i], pv[i]);
                                const int io = mc * 4 + i;
                                o2[io][0] = ffma2(pp, V0.x, o2[io][0]);
                                o2[io][1] = ffma2(pp, V0.y, o2[io][1]);
                                o2[io][2] = ffma2(pp, V1.x, o2[io][2]);
                                o2[io][3] = ffma2(pp, V1.y, o2[io][3]);
                            }
                        }
                        __syncwarp();
                    }
                }
            }
        }

        // ---- store unnormalized partials for this segment slot ----
        {
            float* po = g_pO + (size_t)slot * BM * Dd;
#pragma unroll
            for (int i = 0; i < 8; i++) {
#pragma unroll
                for (int d = 1; d < 8; d <<= 1)
                    l[i] += __shfl_xor_sync(0xffffffffu, l[i], d);
                const int row = tm * 8 + i;
                float* og = po + row * Dd;
                float2 a = unpack2(o2[i][0]);
                float2 b = unpack2(o2[i][1]);
                float2 c = unpack2(o2[i][2]);
                float2 d2 = unpack2(o2[i][3]);
                *(float4*)(og + tn * 4)      = make_float4(a.x, a.y, b.x, b.y);
                *(float4*)(og + 32 + tn * 4) = make_float4(c.x, c.y, d2.x, d2.y);
            }
            if (tn == 0) {
                float* pl = g_pl + (size_t)slot * BM;
#pragma unroll
                for (int i = 0; i < 8; i++) pl[tm * 8 + i] = l[i];
            }
        }

        // block-uniform queue pop
        __syncthreads();
        if (tid == 0) s_slot = atomicAdd(&g_ctr, 1);
        __syncthreads();
        slot = s_slot;
    }
}

// ---------- Stage 3: combine split-K partials, normalize ----------
__global__ __launch_bounds__(256) void combine_kernel(float* __restrict__ out)
{
    const int item = blockIdx.x;
    const int mt = item & 15;
    const int bh = item >> 4;
    const int nseg = NSEG(mt);

    int base = 0;
    for (int m = 15; m > mt; m--) base += NSEG(m) << 5;
    base += bh * nseg;

    const int tid  = threadIdx.x;
    const int rowl = blockIdx.y * 32 + (tid >> 3);
    const int dcol = (tid & 7) * 8;

    float lsum = 0.0f;
    float4 s0 = make_float4(0.f, 0.f, 0.f, 0.f);
    float4 s1 = make_float4(0.f, 0.f, 0.f, 0.f);
    for (int sgi = 0; sgi < nseg; sgi++) {
        const int slot = base + sgi;
        lsum += g_pl[(size_t)slot * BM + rowl];
        const float* po = g_pO + (size_t)slot * BM * Dd + rowl * Dd + dcol;
        float4 a = *(const float4*)po;
        float4 b = *(const float4*)(po + 4);
        s0.x += a.x; s0.y += a.y; s0.z += a.z; s0.w += a.w;
        s1.x += b.x; s1.y += b.y; s1.z += b.z; s1.w += b.w;
    }
    const float inv = 1.0f / lsum;
    const int row_g = mt * BM + rowl;
    float* og = out + ((size_t)bh * Tt + row_g) * Dd + dcol;
    *(float4*)og       = make_float4(s0.x * inv, s0.y * inv, s0.z * inv, s0.w * inv);
    *(float4*)(og + 4) = make_float4(s1.x * inv, s1.y * inv, s1.z * inv, s1.w * inv);
}

// ---------- launch ----------
extern "C" void kernel_launch(void* const* d_in, const int* in_sizes, int n_in,
                              void* d_out, int out_size)
{
    const float* q  = (const float*)d_in[0];
    const float* k  = (const float*)d_in[1];
    const float* v  = (const float*)d_in[2];
    const float* Wq = (const float*)d_in[3];
    const float* Wk = (const float*)d_in[4];
    const float* c1 = (const float*)d_in[5];
    const float* c2 = (const float*)d_in[6];
    float* out = (float*)d_out;

    cudaFuncSetAttribute(flash_kernel,
                         cudaFuncAttributeMaxDynamicSharedMemorySize, SMEM_BYTES);

    dim3 pg(BHn, Tt / 64, 2);
    proj_kernel<<<pg, 256>>>(q, k, Wq, Wk, c1, c2);

    flash_kernel<<<NBLK, NTHREADS, SMEM_BYTES>>>(v);

    dim3 cg(BHn * 16, 4);
    combine_kernel<<<cg, 256>>>(out);
}